// round 1
// baseline (speedup 1.0000x reference)
#include <cuda_runtime.h>

// Problem constants (fixed by the reference):
// B=1, C=8, O=8, G=12, X=12, CH=8, CW=40, Xo=Yo=Zo=9
#define HWN   320      // CH*CW = 8*40
#define NB    729      // 9*9*9 output voxels
#define OBN   56       // O*7  (o*7+b)
#define KKN   216      // C*27 (c*27 + fi*9+fj*3+fk)
#define GON   96       // G*O
#define HI    6        // CH-2
#define WI    38       // CW-2
#define ACC_HW 228     // HI*WI
#define VOX   1728     // 12*12*12
#define OUT_ELEMS (GON*VOX*HWN)   // 53,084,160

// Scratch: Q[n][ob][hw]  (52.2 MB) — static device global per harness rules.
__device__ __align__(16) float g_Q[NB * OBN * HWN];

// ---------------------------------------------------------------------------
// Stage 1: Q[n, ob, hw] = sum_{c,f} W[ob, c*27+f] * x[c, (xi+fi,yj+fj,zk+fk), hw]
// One block per n. 320 threads: thread = hw column. acc[56] in registers.
// W reordered into smem [k][ob] so the 56-wide inner loop reads float4 broadcasts.
// ---------------------------------------------------------------------------
extern "C" __global__ void __launch_bounds__(320, 2)
stage1_kernel(const float* __restrict__ x, const float* __restrict__ weight)
{
    extern __shared__ float sm1[];
    float* w_s   = sm1;                    // KKN*OBN = 12096 floats
    int*   rowoff = (int*)(w_s + KKN * OBN); // 217 ints

    const int n   = blockIdx.x;
    const int tid = threadIdx.x;

    // Reorder weight[o][c][f][b] -> w_s[k*56 + (o*7+b)], k = c*27+f
    for (int idx = tid; idx < KKN * OBN; idx += 320) {
        int k = idx / OBN, ob = idx % OBN;
        int c = k / 27,    f  = k % 27;
        int o = ob / 7,    b  = ob % 7;
        w_s[idx] = weight[((o * 8 + c) * 27 + f) * 7 + b];
    }
    const int xi = n / 81, yj = (n / 9) % 9, zk = n % 9;
    for (int k = tid; k < KKN + 1; k += 320) {
        int kc = (k < KKN) ? k : (KKN - 1);
        int c = kc / 27, f = kc % 27;
        int fi = f / 9, fj = (f / 3) % 3, fk = f % 3;
        rowoff[k] = (((c * 12 + xi + fi) * 12 + (yj + fj)) * 12 + (zk + fk)) * HWN;
    }
    __syncthreads();

    float acc[OBN];
    #pragma unroll
    for (int i = 0; i < OBN; i++) acc[i] = 0.f;

    float xv = __ldg(x + rowoff[0] + tid);
    for (int k = 0; k < KKN; k++) {
        // Prefetch next x value one iteration ahead (hides L2 latency).
        float xn = __ldg(x + rowoff[k + 1] + tid);
        const float* wr = w_s + k * OBN;
        #pragma unroll
        for (int q = 0; q < OBN / 4; q++) {
            float4 w4 = *reinterpret_cast<const float4*>(wr + q * 4);
            acc[q * 4 + 0] += w4.x * xv;
            acc[q * 4 + 1] += w4.y * xv;
            acc[q * 4 + 2] += w4.z * xv;
            acc[q * 4 + 3] += w4.w * xv;
        }
        xv = xn;
    }

    float* qo = g_Q + (long long)n * OBN * HWN + tid;
    #pragma unroll
    for (int ob = 0; ob < OBN; ob++) qo[ob * HWN] = acc[ob];
}

// ---------------------------------------------------------------------------
// Zero the non-interior border of the output (float4 stores).
// Interior voxels (x,y,z in [1,9]^3) are written by stage2.
// ---------------------------------------------------------------------------
extern "C" __global__ void zero_border_kernel(float4* __restrict__ out4)
{
    int idx = blockIdx.x * blockDim.x + threadIdx.x;   // over OUT_ELEMS/4
    if (idx >= OUT_ELEMS / 4) return;
    int voxel = (idx / (HWN / 4)) % VOX;               // 320 floats = 80 float4 per plane
    int xx = voxel / 144, yy = (voxel / 12) % 12, zz = voxel % 12;
    bool interior = (xx >= 1 && xx <= 9 && yy >= 1 && yy <= 9 && zz >= 1 && zz <= 9);
    if (!interior) out4[idx] = make_float4(0.f, 0.f, 0.f, 0.f);
}

// ---------------------------------------------------------------------------
// Stage 2 (fused): per-n 3x3 conv over (h,w) through basis, + bias,
// then the T/I/J gather with border replication, scatter into out.
// One block per n, 256 threads (8 warps). Warp w owns o=w, loops g=0..11.
// ---------------------------------------------------------------------------
extern "C" __global__ void __launch_bounds__(256, 1)
stage2_kernel(const float* __restrict__ bias,
              const float* __restrict__ basis,
              const int*   __restrict__ Iin,
              const int*   __restrict__ Jin,
              const int*   __restrict__ Tin,
              const int*   __restrict__ bb,
              float*       __restrict__ out)
{
    extern __shared__ float sm2[];
    float* Qs   = sm2;                       // 56*320 = 17920 floats
    float* accs = Qs + OBN * HWN;            // 96*228 = 21888 floats, [g*8+o][h*38+w]
    float* bas  = accs + GON * ACC_HW;       // 756
    float* bsum = bas + 756;                 // 8
    int*   Ts   = (int*)(bsum + 8);          // 3840
    int*   Is   = Ts + 3840;                 // 320
    int*   Js   = Is + HWN;                  // 320
    int*   bbs  = Js + HWN;                  // 96

    const int n   = blockIdx.x;
    const int tid = threadIdx.x;

    // Load Q tile (coalesced float4), basis, index tables.
    {
        const float4* qsrc = reinterpret_cast<const float4*>(g_Q + (long long)n * OBN * HWN);
        float4* qdst = reinterpret_cast<float4*>(Qs);
        for (int i = tid; i < OBN * HWN / 4; i += 256) qdst[i] = qsrc[i];
    }
    for (int i = tid; i < 756; i += 256) bas[i] = basis[i];
    for (int i = tid; i < 12 * HWN; i += 256) Ts[i] = Tin[i];
    for (int i = tid; i < HWN; i += 256) { Is[i] = Iin[i]; Js[i] = Jin[i]; }
    for (int i = tid; i < GON; i += 256) bbs[i] = bb[i];
    if (tid < 8) {
        float s = 0.f;
        for (int i = 0; i < 27; i++) s += bias[tid * 27 + i];
        bsum[tid] = s;
    }
    __syncthreads();

    const int warp = tid >> 5, lane = tid & 31;
    if (warp < 8) {
        const int o = warp;
        for (int g = 0; g < 12; g++) {
            const float badd = bsum[bbs[g * 8 + o]];
            float a[2][HI];
            #pragma unroll
            for (int p = 0; p < 2; p++)
                #pragma unroll
                for (int h = 0; h < HI; h++) a[p][h] = 0.f;

            #pragma unroll
            for (int b = 0; b < 7; b++) {
                const float* bp = bas + (g * 7 + b) * 9;
                float B00 = bp[0], B01 = bp[1], B02 = bp[2];
                float B10 = bp[3], B11 = bp[4], B12 = bp[5];
                float B20 = bp[6], B21 = bp[7], B22 = bp[8];
                const float* qrow = Qs + (o * 7 + b) * HWN;
                #pragma unroll
                for (int p = 0; p < 2; p++) {
                    int w0 = 32 * p + lane;
                    if (w0 > 37) w0 = 37;          // clamp: inactive lanes compute dup
                    const float* qr = qrow + w0;
                    #pragma unroll
                    for (int hh = 0; hh < 8; hh++) {
                        float q0 = qr[hh * 40], q1 = qr[hh * 40 + 1], q2 = qr[hh * 40 + 2];
                        if (hh <= 5)             a[p][hh]     += B00 * q0 + B01 * q1 + B02 * q2;
                        if (hh >= 1 && hh <= 6)  a[p][hh - 1] += B10 * q0 + B11 * q1 + B12 * q2;
                        if (hh >= 2)             a[p][hh - 2] += B20 * q0 + B21 * q1 + B22 * q2;
                    }
                }
            }
            float* ar = accs + (g * 8 + o) * ACC_HW;
            #pragma unroll
            for (int p = 0; p < 2; p++) {
                int w0 = 32 * p + lane;
                if (w0 < WI) {
                    #pragma unroll
                    for (int h = 0; h < HI; h++) ar[h * WI + w0] = a[p][h] + badd;
                }
            }
        }
    }
    __syncthreads();

    // Gather (T/I/J with border replication) and scatter into output.
    const int xi = n / 81, yj = (n / 9) % 9, zk = n % 9;
    const int voxel = (1 + xi) * 144 + (1 + yj) * 12 + (1 + zk);
    for (int idx = tid; idx < GON * HWN; idx += 256) {
        int go = idx / HWN, hw = idx - go * HWN;
        int g = go >> 3, o = go & 7;
        int t = Ts[g * HWN + hw];
        int ii = Is[hw] - 1;   // in [0,5]
        int jj = Js[hw] - 1;   // in [0,37]
        float v = accs[(t * 8 + o) * ACC_HW + ii * WI + jj];
        out[(go * VOX + voxel) * HWN + hw] = v;
    }
}

// ---------------------------------------------------------------------------
extern "C" void kernel_launch(void* const* d_in, const int* in_sizes, int n_in,
                              void* d_out, int out_size)
{
    const float* x      = (const float*)d_in[0];
    const float* weight = (const float*)d_in[1];
    const float* bias   = (const float*)d_in[2];
    const float* basis  = (const float*)d_in[3];
    const int*   I      = (const int*)d_in[4];
    const int*   J      = (const int*)d_in[5];
    const int*   T      = (const int*)d_in[6];
    const int*   bb     = (const int*)d_in[7];
    float*       out    = (float*)d_out;

    const int smem1 = (KKN * OBN) * 4 + (KKN + 1) * 4;                     // ~49.3 KB
    const int smem2 = (OBN * HWN + GON * ACC_HW + 756 + 8) * 4
                    + (12 * HWN + HWN + HWN + GON) * 4;                    // ~180.6 KB
    cudaFuncSetAttribute(stage1_kernel, cudaFuncAttributeMaxDynamicSharedMemorySize, smem1);
    cudaFuncSetAttribute(stage2_kernel, cudaFuncAttributeMaxDynamicSharedMemorySize, smem2);

    stage1_kernel<<<NB, 320, smem1>>>(x, weight);
    zero_border_kernel<<<(OUT_ELEMS / 4 + 255) / 256, 256>>>((float4*)d_out);
    stage2_kernel<<<NB, 256, smem2>>>(bias, basis, I, J, T, bb, out);
}

// round 2
// speedup vs baseline: 1.2268x; 1.2268x over previous
#include <cuda_runtime.h>

// Problem constants (fixed by the reference):
// B=1, C=8, O=8, G=12, X=12, CH=8, CW=40, Xo=Yo=Zo=9
#define HWN   320      // CH*CW
#define NB    729      // 9*9*9 output voxels
#define OBN   56       // O*7  (ob = o*7+b)
#define KKN   216      // C*27 (k = c*27 + fi*9+fj*3+fk)
#define GON   96       // G*O
#define HI    6        // CH-2
#define WI    38       // CW-2
#define ACC_HW 228     // HI*WI
#define VOX   1728     // 12*12*12
#define QTILE (OBN*HWN)           // 17920 floats per n
#define OUT_ELEMS (GON*VOX*HWN)   // 53,084,160

typedef unsigned long long ull;

__device__ __forceinline__ ull fma2(ull a, ull b, ull c) {
    ull d; asm("fma.rn.f32x2 %0, %1, %2, %3;" : "=l"(d) : "l"(a), "l"(b), "l"(c)); return d;
}
__device__ __forceinline__ ull pack2(float lo, float hi) {
    ull d; asm("mov.b64 %0, {%1, %2};" : "=l"(d) : "f"(lo), "f"(hi)); return d;
}
__device__ __forceinline__ void unpack2(ull v, float& lo, float& hi) {
    asm("mov.b64 {%0, %1}, %2;" : "=f"(lo), "=f"(hi) : "l"(v));
}

// Scratch: Q[n][b*320+hw][o]  (52.2 MB). Layout chosen so stage2 reads all 8 o
// of a tap with 2 LDS.128 (reinterpreted directly as f32x2 pairs).
__device__ __align__(16) float g_Q[NB * QTILE];

// ---------------------------------------------------------------------------
// Stage 1: Q[n, ob, hw] = sum_{c,f} W[ob, c*27+f] * x[c, (xi+fi,yj+fj,zk+fk), hw]
// One block per n, 320 threads (thread = hw column), acc as 28 f32x2 pairs.
// ---------------------------------------------------------------------------
extern "C" __global__ void __launch_bounds__(320, 2)
stage1_kernel(const float* __restrict__ x, const float* __restrict__ weight)
{
    extern __shared__ float sm1[];
    float* w_s    = sm1;                        // KKN*OBN = 12096 floats
    int*   rowoff = (int*)(w_s + KKN * OBN);    // KKN+2 ints

    const int n   = blockIdx.x;
    const int tid = threadIdx.x;

    // Reorder weight[o][c][f][b] -> w_s[k*56 + (o*7+b)]
    for (int idx = tid; idx < KKN * OBN; idx += 320) {
        int k = idx / OBN, ob = idx % OBN;
        int c = k / 27,    f  = k % 27;
        int o = ob / 7,    b  = ob % 7;
        w_s[idx] = weight[((o * 8 + c) * 27 + f) * 7 + b];
    }
    const int xi = n / 81, yj = (n / 9) % 9, zk = n % 9;
    for (int k = tid; k < KKN + 2; k += 320) {
        int kc = (k < KKN) ? k : (KKN - 1);
        int c = kc / 27, f = kc % 27;
        int fi = f / 9, fj = (f / 3) % 3, fk = f % 3;
        rowoff[k] = (((c * 12 + xi + fi) * 12 + (yj + fj)) * 12 + (zk + fk)) * HWN;
    }
    __syncthreads();

    ull acc[28];
    #pragma unroll
    for (int i = 0; i < 28; i++) acc[i] = 0ULL;

    // Prefetch distance 2: per-warp k-period (~280 cyc at full pipe) vs L2 ~262.
    float xv0 = __ldg(x + rowoff[0] + tid);
    float xv1 = __ldg(x + rowoff[1] + tid);
    for (int k = 0; k < KKN; k++) {
        float xn = __ldg(x + rowoff[k + 2] + tid);
        ull xv2 = pack2(xv0, xv0);
        const ulonglong2* wr = (const ulonglong2*)(w_s + k * OBN);  // 14 bcast LDS.128
        #pragma unroll
        for (int j = 0; j < 14; j++) {
            ulonglong2 w2 = wr[j];
            acc[2 * j    ] = fma2(w2.x, xv2, acc[2 * j    ]);
            acc[2 * j + 1] = fma2(w2.y, xv2, acc[2 * j + 1]);
        }
        xv0 = xv1; xv1 = xn;
    }

    float accf[56];
    #pragma unroll
    for (int i = 0; i < 28; i++) unpack2(acc[i], accf[2 * i], accf[2 * i + 1]);

    // Store transposed: g_Q[n][(b*320+hw)*8 + o], two STG.128 per b.
    float* qo = g_Q + (size_t)n * QTILE + tid * 8;
    #pragma unroll
    for (int b = 0; b < 7; b++) {
        float4 v0 = make_float4(accf[b], accf[7 + b], accf[14 + b], accf[21 + b]);
        float4 v1 = make_float4(accf[28 + b], accf[35 + b], accf[42 + b], accf[49 + b]);
        *reinterpret_cast<float4*>(qo + b * 2560)     = v0;
        *reinterpret_cast<float4*>(qo + b * 2560 + 4) = v1;
    }
}

// ---------------------------------------------------------------------------
// Zero the non-interior border of the output (float4 stores).
// ---------------------------------------------------------------------------
extern "C" __global__ void zero_border_kernel(float4* __restrict__ out4)
{
    int idx = blockIdx.x * blockDim.x + threadIdx.x;
    if (idx >= OUT_ELEMS / 4) return;
    int voxel = (idx / (HWN / 4)) % VOX;
    int xx = voxel / 144, yy = (voxel / 12) % 12, zz = voxel % 12;
    bool interior = (xx >= 1 && xx <= 9 && yy >= 1 && yy <= 9 && zz >= 1 && zz <= 9);
    if (!interior) out4[idx] = make_float4(0.f, 0.f, 0.f, 0.f);
}

// ---------------------------------------------------------------------------
// Stage 2: register-tile GEMM acc[go, hw'] = sum_{k=63} basis[g,k] * Qtap[o,k,hw']
// + bias, then T/I/J gather with border replication, scatter into out.
// One block per n, 256 threads; thread = one (h,w) of the 228 valid outputs.
// acc = 6 g x 4 o-pairs (f32x2) per g-half, two g-halves.
// ---------------------------------------------------------------------------
extern "C" __global__ void __launch_bounds__(256, 1)
stage2_kernel(const float* __restrict__ bias,
              const float* __restrict__ basis,
              const int*   __restrict__ Iin,
              const int*   __restrict__ Jin,
              const int*   __restrict__ Tin,
              const int*   __restrict__ bb,
              float*       __restrict__ out)
{
    extern __shared__ char sm2raw[];
    ull*   basP = (ull*)sm2raw;                  // [k=63][g=12] duplicated pairs
    float* Qs   = (float*)(basP + 756);          // 17920 floats, [b*320+pos][o]
    float* accs = Qs + QTILE;                    // 96*228
    float* bsum = accs + GON * ACC_HW;           // 8
    int*   Ts   = (int*)(bsum + 8);              // 3840
    int*   Is   = Ts + 3840;                     // 320
    int*   Js   = Is + HWN;                      // 320
    int*   bbs  = Js + HWN;                      // 96

    const int n   = blockIdx.x;
    const int tid = threadIdx.x;

    // Coalesced Q tile copy (layout already matches).
    {
        const float4* src = (const float4*)(g_Q + (size_t)n * QTILE);
        float4* dst = (float4*)Qs;
        for (int i = tid; i < QTILE / 4; i += 256) dst[i] = src[i];
    }
    // basis[g][b][u][v] -> basP[(b*9+uv)*12 + g], value duplicated into both halves.
    for (int i = tid; i < 756; i += 256) {
        float v = basis[i];
        int g = i / 63, k = i % 63;
        basP[k * 12 + g] = pack2(v, v);
    }
    for (int i = tid; i < 12 * HWN; i += 256) Ts[i] = Tin[i];
    for (int i = tid; i < HWN; i += 256) { Is[i] = Iin[i]; Js[i] = Jin[i]; }
    for (int i = tid; i < GON; i += 256) bbs[i] = bb[i];
    if (tid < 8) {
        float s = 0.f;
        for (int i = 0; i < 27; i++) s += bias[tid * 27 + i];
        bsum[tid] = s;
    }
    __syncthreads();

    if (tid < ACC_HW) {
        const int h = tid / WI, w = tid % WI;
        const float* qb = Qs + (h * 40 + w) * 8;
        #pragma unroll
        for (int gh = 0; gh < 2; gh++) {
            ull acc[6][4];
            #pragma unroll
            for (int g = 0; g < 6; g++)
                #pragma unroll
                for (int p = 0; p < 4; p++) acc[g][p] = 0ULL;

            #pragma unroll 1
            for (int b = 0; b < 7; b++) {
                const float* qbb = qb + b * 2560;
                const ull*   bpp = basP + b * 9 * 12 + gh * 6;
                #pragma unroll
                for (int uv = 0; uv < 9; uv++) {
                    int u = uv / 3, v = uv - u * 3;
                    const ulonglong2* q4 = (const ulonglong2*)(qbb + (u * 40 + v) * 8);
                    ulonglong2 qA = q4[0];   // o pairs (0,1),(2,3)
                    ulonglong2 qB = q4[1];   // o pairs (4,5),(6,7)
                    const ull* bk = bpp + uv * 12;
                    #pragma unroll
                    for (int g = 0; g < 6; g++) {
                        ull bv = bk[g];      // LDS.64 broadcast (pre-duplicated)
                        acc[g][0] = fma2(qA.x, bv, acc[g][0]);
                        acc[g][1] = fma2(qA.y, bv, acc[g][1]);
                        acc[g][2] = fma2(qB.x, bv, acc[g][2]);
                        acc[g][3] = fma2(qB.y, bv, acc[g][3]);
                    }
                }
            }
            #pragma unroll
            for (int g = 0; g < 6; g++) {
                int gg = gh * 6 + g;
                #pragma unroll
                for (int p = 0; p < 4; p++) {
                    float f0, f1; unpack2(acc[g][p], f0, f1);
                    int o0 = 2 * p, o1 = 2 * p + 1;
                    accs[(gg * 8 + o0) * ACC_HW + tid] = f0 + bsum[bbs[gg * 8 + o0]];
                    accs[(gg * 8 + o1) * ACC_HW + tid] = f1 + bsum[bbs[gg * 8 + o1]];
                }
            }
        }
    }
    __syncthreads();

    // Gather (T/I/J with border replication) and scatter into output.
    const int xi = n / 81, yj = (n / 9) % 9, zk = n % 9;
    const int voxel = (1 + xi) * 144 + (1 + yj) * 12 + (1 + zk);
    for (int idx = tid; idx < GON * HWN; idx += 256) {
        int go = idx / HWN, hw = idx - go * HWN;
        int g = go >> 3, o = go & 7;
        int t = Ts[g * HWN + hw];
        int ii = Is[hw] - 1;   // in [0,5]
        int jj = Js[hw] - 1;   // in [0,37]
        float v = accs[(t * 8 + o) * ACC_HW + ii * WI + jj];
        out[((size_t)go * VOX + voxel) * HWN + hw] = v;
    }
}

// ---------------------------------------------------------------------------
extern "C" void kernel_launch(void* const* d_in, const int* in_sizes, int n_in,
                              void* d_out, int out_size)
{
    const float* x      = (const float*)d_in[0];
    const float* weight = (const float*)d_in[1];
    const float* bias   = (const float*)d_in[2];
    const float* basis  = (const float*)d_in[3];
    const int*   I      = (const int*)d_in[4];
    const int*   J      = (const int*)d_in[5];
    const int*   T      = (const int*)d_in[6];
    const int*   bb     = (const int*)d_in[7];
    float*       out    = (float*)d_out;

    const int smem1 = (KKN * OBN) * 4 + (KKN + 2) * 4;                      // ~49.3 KB
    const int smem2 = 756 * 8 + (QTILE + GON * ACC_HW + 8) * 4
                    + (12 * HWN + HWN + HWN + GON) * 4;                     // ~183.6 KB
    cudaFuncSetAttribute(stage1_kernel, cudaFuncAttributeMaxDynamicSharedMemorySize, smem1);
    cudaFuncSetAttribute(stage2_kernel, cudaFuncAttributeMaxDynamicSharedMemorySize, smem2);

    stage1_kernel<<<NB, 320, smem1>>>(x, weight);
    zero_border_kernel<<<(OUT_ELEMS / 4 + 255) / 256, 256>>>((float4*)d_out);
    stage2_kernel<<<NB, 256, smem2>>>(bias, basis, I, J, T, bb, out);
}